// round 13
// baseline (speedup 1.0000x reference)
#include <cuda_runtime.h>

// ----------------------------------------------------------------------------
// RNNDecoder: 3-layer GRU (H=128), T=256, B=1024, fc head (out=2).
//
// R10: 256 CTAs x 256 threads (BC=4, 2-way K-split), 2 CTAs per SM.
// The two co-resident CTAs have INDEPENDENT barrier domains and drift out of
// phase, so one CTA's FFMA2 stream fills the other's combine/barrier troughs
// (single-CTA phase lock was the diagnosed wall across R7-R9).
//   - Thread (grp,u): u = hidden unit (r,z,n gate rows), grp = K-half (64 k).
//     768 FFMA2/thread/cell; batch-pair f32x2 packing.
//   - Cost accepted: per-SM weight wavefronts double (both CTAs read all
//     weights); L1 -> ~8.7K wf/cell vs FMA 6.1K cyc.
//   - __launch_bounds__(256, 2): regs <= 128 so 2 CTAs fit the RF exactly.
//   - R9's overlap kept: combine(i) co-scheduled with hGEMV(i+1).
//   - All register-array indices compile-time (templated store/combine).
// ----------------------------------------------------------------------------

namespace {
constexpr int LAYERS = 3;
constexpr int H      = 128;
constexpr int G3     = 3 * H;
constexpr int T      = 256;
constexpr int BC     = 4;
constexpr int NTHR   = 256;
constexpr int NBLK   = 256;        // 1024 / BC
constexpr int KKH    = 16;         // float4 K-chunks per K-half
}

typedef unsigned long long ull;

// Transposed weights: [l][kkp][g(r,z,n)][tid] float4,
// tid = grp*128 + u -> (unit u, K-half grp).
__device__ float4 g_wih[LAYERS * KKH * 3 * NTHR];
__device__ float4 g_whh[LAYERS * KKH * 3 * NTHR];

__global__ void prep_kernel(const float* __restrict__ wih,
                            const float* __restrict__ whh) {
  const int PER = LAYERS * KKH * 3 * NTHR;
  int idx = blockIdx.x * blockDim.x + threadIdx.x;
  if (idx >= 2 * PER) return;
  int arr = idx / PER;
  int r   = idx % PER;
  int t   = r % NTHR;
  int g   = (r / NTHR) % 3;
  int kkp = (r / (NTHR * 3)) % KKH;
  int l   = r / (NTHR * 3 * KKH);
  int u   = t & 127, grp = t >> 7;
  int k4  = grp * KKH + kkp;
  const float* src = (arr ? whh : wih) + (l * G3 + g * 128 + u) * H + k4 * 4;
  float4* dst = arr ? g_whh : g_wih;
  dst[((l * KKH + kkp) * 3 + g) * NTHR + t] =
      *reinterpret_cast<const float4*>(src);
}

__device__ __forceinline__ void ffma2(ull& a, ull w, ull x) {
  asm("fma.rn.f32x2 %0, %1, %2, %0;" : "+l"(a) : "l"(w), "l"(x));
}
__device__ __forceinline__ void fadd2(ull& a, ull b) {
  asm("add.rn.f32x2 %0, %0, %1;" : "+l"(a) : "l"(b));
}
__device__ __forceinline__ ull dup2(float w) {
  ull r;
  asm("mov.b64 %0, {%1, %1};" : "=l"(r) : "f"(w));
  return r;
}
__device__ __forceinline__ float2 unpk(ull v) {
  float lo, hi;
  asm("mov.b64 {%0, %1}, %2;" : "=f"(lo), "=f"(hi) : "l"(v));
  return make_float2(lo, hi);
}
__device__ __forceinline__ ull pack2(float lo, float hi) {
  ull r;
  asm("mov.b64 %0, {%1, %2};" : "=l"(r) : "f"(lo), "f"(hi));
  return r;
}
__device__ __forceinline__ float sigm(float x) {
  return __fdividef(1.0f, 1.0f + __expf(-x));
}
__device__ __forceinline__ float tanh_fast(float v) {
  float a = fabsf(v);
  float e = __expf(-2.0f * a);
  float r = __fdividef(1.0f - e, 1.0f + e);
  return copysignf(r, v);
}
__device__ __forceinline__ float comp(const float4& v, int e) {
  return e == 0 ? v.x : e == 1 ? v.y : e == 2 ? v.z : v.w;
}

// One array's half-gemv over this thread's K-half (64 k): 3 gate rows x
// 4 batch (2 f32x2 pairs). 48 LDG.128, 64 LDS.128, 384 FFMA2 per thread.
__device__ __forceinline__ void half_gemv(const float* __restrict__ act,
                                          const float4* __restrict__ wp,
                                          ull (&acc)[3][2]) {
#pragma unroll
  for (int g = 0; g < 3; g++) {
    acc[g][0] = 0ull;
    acc[g][1] = 0ull;
  }
  float4 wv[3], wn[3];
#pragma unroll
  for (int i = 0; i < 3; i++) wn[i] = wp[i * NTHR];

#pragma unroll
  for (int kkp = 0; kkp < KKH; kkp++) {
#pragma unroll
    for (int i = 0; i < 3; i++) wv[i] = wn[i];
    if (kkp < KKH - 1) {
#pragma unroll
      for (int i = 0; i < 3; i++) wn[i] = wp[((kkp + 1) * 3 + i) * NTHR];
    }
#pragma unroll
    for (int e = 0; e < 4; e++) {
      // activations [k][b], BC=4 -> one LDS.128 = both batch pairs of k.
      ulonglong2 v = *reinterpret_cast<const ulonglong2*>(
          act + (kkp * 4 + e) * 4);
#pragma unroll
      for (int g = 0; g < 3; g++) {
        ull w2 = dup2(comp(wv[g], e));
        ffma2(acc[g][0], w2, v.x);
        ffma2(acc[g][1], w2, v.y);
      }
    }
  }
}

// Store partials of the non-owned batch-pair P into exchange region P.
template <int P>
__device__ __forceinline__ void store_pair(ull* __restrict__ sp, int u,
                                           ull r2, ull z2, ull nx2, ull nh2) {
  ull* base = sp + P * 512 + u;
  base[0]   = r2;
  base[128] = z2;
  base[256] = nx2;
  base[384] = nh2;
}

// Combine owned batch-pair P: add partner partials, GRU gate math, write h.
template <int P>
__device__ __forceinline__ void combine_pair(ull r2, ull z2, ull nx2, ull nh2,
                                             const ull* __restrict__ sp, int u,
                                             const float* __restrict__ sb,
                                             float* __restrict__ hl,
                                             float* __restrict__ sx) {
  const ull* base = sp + P * 512 + u;
  fadd2(r2,  base[0]);
  fadd2(z2,  base[128]);
  fadd2(nx2, base[256]);
  fadd2(nh2, base[384]);
  float brz_r = sb[u], brz_z = sb[128 + u];
  float bn_x = sb[256 + u], bn_h = sb[384 + u];
  float2 rr = unpk(r2), zz = unpk(z2), xx = unpk(nx2), hh = unpk(nh2);
  float hp0 = hl[u * 4 + 2 * P], hp1 = hl[u * 4 + 2 * P + 1];
  float r0 = sigm(rr.x + brz_r), z0 = sigm(zz.x + brz_z);
  float n0 = tanh_fast(xx.x + bn_x + r0 * (hh.x + bn_h));
  float h0 = fmaf(z0, hp0 - n0, n0);
  float r1 = sigm(rr.y + brz_r), z1 = sigm(zz.y + brz_z);
  float n1 = tanh_fast(xx.y + bn_x + r1 * (hh.y + bn_h));
  float h1 = fmaf(z1, hp1 - n1, n1);
  ull o = pack2(h0, h1);
  *reinterpret_cast<ull*>(hl + u * 4 + 2 * P) = o;
  *reinterpret_cast<ull*>(sx + u * 4 + 2 * P) = o;
}

__global__ void __launch_bounds__(NTHR, 2)
gru_kernel(const float* __restrict__ hiddens,
           const float* __restrict__ b_ih,
           const float* __restrict__ b_hh,
           const float* __restrict__ fc_w,
           const float* __restrict__ fc_b,
           float* __restrict__ out) {
  __shared__ __align__(16) float s_x[H * BC];            // [k][b]
  __shared__ __align__(16) float s_h[LAYERS * H * BC];   // [l][k][b]
  __shared__ __align__(16) ull   s_p[2 * 4 * 128];       // [pair][v][u]
  __shared__ float s_fcw[2 * H];
  __shared__ float s_fcb[2];
  __shared__ float s_bias[LAYERS * 4 * 128];             // [l][v][u]

  const int tid = threadIdx.x;
  const int u   = tid & 127;
  const int grp = tid >> 7;                              // K-half & owned pair
  const int b0  = blockIdx.x * BC;

  if (tid < 128) {
#pragma unroll
    for (int l = 0; l < LAYERS; l++) {
      s_bias[l * 512 + 0 * 128 + tid] =
          b_ih[l * G3 + tid] + b_hh[l * G3 + tid];
      s_bias[l * 512 + 1 * 128 + tid] =
          b_ih[l * G3 + 128 + tid] + b_hh[l * G3 + 128 + tid];
      s_bias[l * 512 + 2 * 128 + tid] = b_ih[l * G3 + 256 + tid];
      s_bias[l * 512 + 3 * 128 + tid] = b_hh[l * G3 + 256 + tid];
    }
  }
  s_fcw[tid] = fc_w[tid];
  if (tid < 2) s_fcb[tid] = fc_b[tid];

  // h init: hiddens[b][l][k] -> s_h[l][k][b]
  for (int i = tid; i < LAYERS * H * BC; i += NTHR) {
    int l = i >> 9, rem = i & 511, k = rem >> 2, b = rem & 3;
    s_h[i] = hiddens[(b0 + b) * (LAYERS * H) + l * H + k];
  }
  for (int i = tid; i < H * BC; i += NTHR) s_x[i] = 0.0f;
  __syncthreads();

  // Prologue: h half-gemv of cell 0 (layer 0).
  ull acch[3][2];
  half_gemv(s_h + grp * 256, g_whh + tid, acch);

  for (int t = 0; t < T; t++) {
#pragma unroll 1
    for (int l = 0; l < LAYERS; l++) {
      float* __restrict__ hl = s_h + l * (H * BC);

      // x half-gemv of the current cell (s_x stable since last barrier).
      ull accx[3][2];
      half_gemv(s_x + grp * 256, g_wih + l * (KKH * 3 * NTHR) + tid, accx);

      // Merge r,z across arrays (only sums matter).
      ull rzr0 = accx[0][0]; fadd2(rzr0, acch[0][0]);
      ull rzr1 = accx[0][1]; fadd2(rzr1, acch[0][1]);
      ull rzz0 = accx[1][0]; fadd2(rzz0, acch[1][0]);
      ull rzz1 = accx[1][1]; fadd2(rzz1, acch[1][1]);

      // Store non-owned pair; grp0 owns pair0, grp1 owns pair1.
      if (grp == 0) store_pair<1>(s_p, u, rzr1, rzz1, accx[2][1], acch[2][1]);
      else          store_pair<0>(s_p, u, rzr0, rzz0, accx[2][0], acch[2][0]);
      __syncthreads();                             // B1: partials visible

      // combine(i) co-scheduled with hGEMV(i+1) (reads older s_h layer).
      const float* sb = s_bias + l * 512;
      if (grp == 0)
        combine_pair<0>(rzr0, rzz0, accx[2][0], acch[2][0], s_p, u, sb,
                        hl, s_x);
      else
        combine_pair<1>(rzr1, rzz1, accx[2][1], acch[2][1], s_p, u, sb,
                        hl, s_x);

      int ln = (l == LAYERS - 1) ? 0 : l + 1;      // next cell's layer
      half_gemv(s_h + ln * (H * BC) + grp * 256,
                g_whh + ln * (KKH * 3 * NTHR) + tid, acch);
      __syncthreads();                             // B2: s_x visible

      // fc head on top-layer output: 8 outputs (2 out x 4 batch) x 16 lanes.
      if (l == 2 && tid < 128) {
        int oid = tid >> 4, s = tid & 15;
        int o = oid & 1, b = oid >> 1;
        float p = 0.0f;
#pragma unroll
        for (int m = 0; m < 8; m++)
          p = fmaf(s_fcw[o * H + s * 8 + m], s_x[(s * 8 + m) * 4 + b], p);
        p += __shfl_down_sync(0xffffffffu, p, 8, 16);
        p += __shfl_down_sync(0xffffffffu, p, 4, 16);
        p += __shfl_down_sync(0xffffffffu, p, 2, 16);
        p += __shfl_down_sync(0xffffffffu, p, 1, 16);
        if (s == 0) out[((b0 + b) * T + t) * 2 + o] = p + s_fcb[o];
      }
      // fc reads of s_x finish before the next cell's combine rewrites s_x
      // (that rewrite sits behind the next cell's B1).
    }
  }
}

extern "C" void kernel_launch(void* const* d_in, const int* in_sizes, int n_in,
                              void* d_out, int out_size) {
  (void)in_sizes; (void)n_in; (void)out_size;
  const float* hiddens = (const float*)d_in[0];
  const float* W_ih    = (const float*)d_in[1];
  const float* W_hh    = (const float*)d_in[2];
  const float* b_ih    = (const float*)d_in[3];
  const float* b_hh    = (const float*)d_in[4];
  const float* fc_w    = (const float*)d_in[5];
  const float* fc_b    = (const float*)d_in[6];
  float* out = (float*)d_out;

  const int prep_elems = 2 * LAYERS * KKH * 3 * NTHR;
  prep_kernel<<<(prep_elems + 255) / 256, 256>>>(W_ih, W_hh);
  gru_kernel<<<NBLK, NTHR>>>(hiddens, b_ih, b_hh, fc_w, fc_b, out);
}

// round 14
// speedup vs baseline: 1.1902x; 1.1902x over previous
#include <cuda_runtime.h>

// ----------------------------------------------------------------------------
// RNNDecoder: 3-layer GRU (H=128), T=256, B=1024, fc head (out=2).
//
// R12: 128 CTAs x 256 threads, R=2 units/thread, G=4 K-split, 1 CTA/SM.
//   - Thread (grp, v): owns hidden units v and v+64, K-slice grp*32..+32.
//     Each activation LDS now feeds 6 gate rows -> activation wavefronts
//     halve vs R9 (L1 was the measured wall at 66%).
//   - r,z accumulators merged across W_ih/W_hh (only the sum matters):
//     acc[2 units][r,z,nx,nh][4 batch-pairs] = 64 regs, all indices
//     compile-time. launch_bounds(256,1) -> up to 255 regs, no spill.
//   - R9 cross-cell overlap kept: hGEMV(i+1) (re-initializing acc) is
//     co-scheduled with combine(i); weights double-buffered one chunk ahead.
//   - Cheap G=4 exchange: 24 ST.64 + 24 LD.64 per thread, conflict-free.
// ----------------------------------------------------------------------------

namespace {
constexpr int LAYERS = 3;
constexpr int H      = 128;
constexpr int G3     = 3 * H;
constexpr int T      = 256;
constexpr int BC     = 8;
constexpr int NTHR   = 256;
constexpr int NBLK   = 128;        // 1024 / BC
constexpr int KCH    = 8;          // float4 K-chunks per 32-k slice

// dynamic smem layout (bytes)
constexpr int SMEM_X    = 0;       // float[1024]   s_x  [k][b]
constexpr int SMEM_H    = 4096;    // float[3072]   s_h  [l][k][b]
constexpr int SMEM_P    = 16384;   // ull[6144]     exchange [P][c][val][U]
constexpr int SMEM_FCW  = 65536;   // float[256]
constexpr int SMEM_FCB  = 66560;   // float[2]
constexpr int SMEM_BIAS = 66568;   // float[3*4*128] = [l][val][u]
constexpr int SMEM_TOTAL = 66568 + 6144;
}

typedef unsigned long long ull;

// Transposed weights: [l][kkp][slot(6 = unit-delta*3 + gate)][t] float4,
// t = grp*64 + v -> (units v, v+64; K-slice grp).
__device__ float4 g_wih[LAYERS * KCH * 6 * NTHR];
__device__ float4 g_whh[LAYERS * KCH * 6 * NTHR];

__global__ void prep_kernel(const float* __restrict__ wih,
                            const float* __restrict__ whh) {
  const int PER = LAYERS * KCH * 6 * NTHR;   // 36864
  int idx = blockIdx.x * blockDim.x + threadIdx.x;
  if (idx >= 2 * PER) return;
  int arr  = idx / PER;
  int r    = idx % PER;
  int t    = r % NTHR;
  int slot = (r / NTHR) % 6;
  int kkp  = (r / (NTHR * 6)) % KCH;
  int l    = r / (NTHR * 6 * KCH);
  int d    = slot / 3, g = slot % 3;
  int v    = t & 63, grp = t >> 6;
  int unit = v + 64 * d;
  const float* src =
      (arr ? whh : wih) + (l * G3 + g * 128 + unit) * H + (grp * KCH + kkp) * 4;
  float4* dst = arr ? g_whh : g_wih;
  dst[((l * KCH + kkp) * 6 + slot) * NTHR + t] =
      *reinterpret_cast<const float4*>(src);
}

__device__ __forceinline__ void ffma2(ull& a, ull w, ull x) {
  asm("fma.rn.f32x2 %0, %1, %2, %0;" : "+l"(a) : "l"(w), "l"(x));
}
__device__ __forceinline__ void fadd2(ull& a, ull b) {
  asm("add.rn.f32x2 %0, %0, %1;" : "+l"(a) : "l"(b));
}
__device__ __forceinline__ ull dup2(float w) {
  ull r;
  asm("mov.b64 %0, {%1, %1};" : "=l"(r) : "f"(w));
  return r;
}
__device__ __forceinline__ float2 unpk(ull v) {
  float lo, hi;
  asm("mov.b64 {%0, %1}, %2;" : "=f"(lo), "=f"(hi) : "l"(v));
  return make_float2(lo, hi);
}
__device__ __forceinline__ ull pack2(float lo, float hi) {
  ull r;
  asm("mov.b64 %0, {%1, %2};" : "=l"(r) : "f"(lo), "f"(hi));
  return r;
}
__device__ __forceinline__ float sigm(float x) {
  return __fdividef(1.0f, 1.0f + __expf(-x));
}
__device__ __forceinline__ float tanh_fast(float v) {
  float a = fabsf(v);
  float e = __expf(-2.0f * a);
  float r = __fdividef(1.0f - e, 1.0f + e);
  return copysignf(r, v);
}
__device__ __forceinline__ float comp(const float4& v, int e) {
  return e == 0 ? v.x : e == 1 ? v.y : e == 2 ? v.z : v.w;
}

// Half-gemv over this thread's 32-k slice for 2 units x 3 gates x 8 batch.
// ARR=1 (W_hh, pipelined for the NEXT cell): zero-inits acc, fills r,z,nh.
// ARR=0 (W_ih, current cell): accumulates into r,z,nx.
// acc[d][0]=r (both arrays merged), [1]=z (merged), [2]=nx, [3]=nh.
template <int ARR>
__device__ __forceinline__ void half_gemv(const float* __restrict__ act,
                                          const float4* __restrict__ wp,
                                          ull (&acc)[2][4][4]) {
  if (ARR == 1) {
#pragma unroll
    for (int d = 0; d < 2; d++)
#pragma unroll
      for (int g = 0; g < 4; g++)
#pragma unroll
        for (int q = 0; q < 4; q++) acc[d][g][q] = 0ull;
  }
  float4 wv[6], wn[6];
#pragma unroll
  for (int i = 0; i < 6; i++) wn[i] = wp[i * NTHR];

#pragma unroll
  for (int kkp = 0; kkp < KCH; kkp++) {
#pragma unroll
    for (int i = 0; i < 6; i++) wv[i] = wn[i];
    if (kkp < KCH - 1) {
#pragma unroll
      for (int i = 0; i < 6; i++) wn[i] = wp[((kkp + 1) * 6 + i) * NTHR];
    }
#pragma unroll
    for (int e = 0; e < 4; e++) {
      int k8 = (kkp * 4 + e) * 8;
      ulonglong2 a0 = *reinterpret_cast<const ulonglong2*>(act + k8);
      ulonglong2 a1 = *reinterpret_cast<const ulonglong2*>(act + k8 + 4);
#pragma unroll
      for (int d = 0; d < 2; d++) {
#pragma unroll
        for (int g = 0; g < 3; g++) {
          const int tgt = (g < 2) ? g : (ARR == 0 ? 2 : 3);
          ull w2 = dup2(comp(wv[d * 3 + g], e));
          ffma2(acc[d][tgt][0], w2, a0.x);
          ffma2(acc[d][tgt][1], w2, a0.y);
          ffma2(acc[d][tgt][2], w2, a1.x);
          ffma2(acc[d][tgt][3], w2, a1.y);
        }
      }
    }
  }
}

// Combine owned pair P for both units: add 3 partner partials, GRU gate math,
// write new hidden state. P compile-time -> constant acc/register indices.
template <int P>
__device__ __forceinline__ void combine_pair(const ull (&acc)[2][4][4],
                                             const ull* __restrict__ sp,
                                             int v,
                                             const float* __restrict__ sb,
                                             float* __restrict__ hl,
                                             float* __restrict__ sx) {
#pragma unroll
  for (int d = 0; d < 2; d++) {
    int U = v + 64 * d;
    ull r2  = acc[d][0][P];
    ull z2  = acc[d][1][P];
    ull nx2 = acc[d][2][P];
    ull nh2 = acc[d][3][P];
#pragma unroll
    for (int c = 0; c < 3; c++) {
      const ull* base = sp + ((P * 3 + c) * 4) * 128 + U;
      fadd2(r2,  base[0]);
      fadd2(z2,  base[128]);
      fadd2(nx2, base[256]);
      fadd2(nh2, base[384]);
    }
    float brz_r = sb[U], brz_z = sb[128 + U];
    float bn_x = sb[256 + U], bn_h = sb[384 + U];
    float2 rr = unpk(r2), zz = unpk(z2), xx = unpk(nx2), hh = unpk(nh2);
    float hp0 = hl[U * 8 + 2 * P], hp1 = hl[U * 8 + 2 * P + 1];
    float r0 = sigm(rr.x + brz_r), z0 = sigm(zz.x + brz_z);
    float n0 = tanh_fast(xx.x + bn_x + r0 * (hh.x + bn_h));
    float h0 = fmaf(z0, hp0 - n0, n0);
    float r1 = sigm(rr.y + brz_r), z1 = sigm(zz.y + brz_z);
    float n1 = tanh_fast(xx.y + bn_x + r1 * (hh.y + bn_h));
    float h1 = fmaf(z1, hp1 - n1, n1);
    ull o = pack2(h0, h1);
    *reinterpret_cast<ull*>(hl + U * 8 + 2 * P) = o;
    *reinterpret_cast<ull*>(sx + U * 8 + 2 * P) = o;
  }
}

__global__ void __launch_bounds__(NTHR, 1)
gru_kernel(const float* __restrict__ hiddens,
           const float* __restrict__ b_ih,
           const float* __restrict__ b_hh,
           const float* __restrict__ fc_w,
           const float* __restrict__ fc_b,
           float* __restrict__ out) {
  extern __shared__ __align__(16) char dsm[];
  float* s_x    = reinterpret_cast<float*>(dsm + SMEM_X);
  float* s_h    = reinterpret_cast<float*>(dsm + SMEM_H);
  ull*   s_p    = reinterpret_cast<ull*>(dsm + SMEM_P);
  float* s_fcw  = reinterpret_cast<float*>(dsm + SMEM_FCW);
  float* s_fcb  = reinterpret_cast<float*>(dsm + SMEM_FCB);
  float* s_bias = reinterpret_cast<float*>(dsm + SMEM_BIAS);

  const int tid = threadIdx.x;
  const int v   = tid & 63;
  const int grp = tid >> 6;           // K-slice & owned batch-pair
  const int b0  = blockIdx.x * BC;

  // Biases -> smem: [l][val][u], val = {r(bi+bh), z(bi+bh), n_x(bi), n_h(bh)}.
  if (tid < 128) {
#pragma unroll
    for (int l = 0; l < LAYERS; l++) {
      s_bias[l * 512 + 0 * 128 + tid] =
          b_ih[l * G3 + tid] + b_hh[l * G3 + tid];
      s_bias[l * 512 + 1 * 128 + tid] =
          b_ih[l * G3 + 128 + tid] + b_hh[l * G3 + 128 + tid];
      s_bias[l * 512 + 2 * 128 + tid] = b_ih[l * G3 + 256 + tid];
      s_bias[l * 512 + 3 * 128 + tid] = b_hh[l * G3 + 256 + tid];
    }
  }
  s_fcw[tid] = fc_w[tid];
  if (tid < 2) s_fcb[tid] = fc_b[tid];

  // h init: hiddens[b][l][k] -> s_h[l][k][b]
  for (int i = tid; i < LAYERS * H * BC; i += NTHR) {
    int l = i >> 10, rem = i & 1023, k = rem >> 3, b = rem & 7;
    s_h[i] = hiddens[(b0 + b) * (LAYERS * H) + l * H + k];
  }
  for (int i = tid; i < H * BC; i += NTHR) s_x[i] = 0.0f;
  __syncthreads();

  // Prologue: W_hh half-gemv of cell 0 (layer 0) initializes acc.
  ull acc[2][4][4];
  half_gemv<1>(s_h + grp * 256, g_whh + tid, acc);

  for (int t = 0; t < T; t++) {
#pragma unroll 1
    for (int l = 0; l < LAYERS; l++) {
      float* __restrict__ hl = s_h + l * (H * BC);

      // W_ih half-gemv of the current cell accumulates into acc.
      half_gemv<0>(s_x + grp * 256, g_wih + l * (KCH * 6 * NTHR) + tid, acc);

      // Store partials for the 3 batch-pairs this group does not own.
#pragma unroll
      for (int q = 0; q < 4; q++) {
        if (q == grp) continue;                  // runtime guard, const q
        int c = grp - (grp > q ? 1 : 0);
#pragma unroll
        for (int d = 0; d < 2; d++) {
          int U = v + 64 * d;
          ull* base = s_p + ((q * 3 + c) * 4) * 128 + U;
          base[0]   = acc[d][0][q];
          base[128] = acc[d][1][q];
          base[256] = acc[d][2][q];
          base[384] = acc[d][3][q];
        }
      }
      __syncthreads();                           // B1: partials visible

      // combine(i) co-scheduled with hGEMV(i+1): the next cell's W_hh gemv
      // reads s_h[ln] (written 2-3 cells ago) and re-initializes acc; the
      // combine consumes this cell's owned acc values first (reg data dep).
      const float* sb = s_bias + l * 512;
      if (grp == 0)      combine_pair<0>(acc, s_p, v, sb, hl, s_x);
      else if (grp == 1) combine_pair<1>(acc, s_p, v, sb, hl, s_x);
      else if (grp == 2) combine_pair<2>(acc, s_p, v, sb, hl, s_x);
      else               combine_pair<3>(acc, s_p, v, sb, hl, s_x);

      int ln = (l == LAYERS - 1) ? 0 : l + 1;    // next cell's layer
      half_gemv<1>(s_h + ln * (H * BC) + grp * 256,
                   g_whh + ln * (KCH * 6 * NTHR) + tid, acc);
      __syncthreads();                           // B2: s_x visible

      // fc head on top-layer output: 16 outputs (2 out x 8 batch) x 16 lanes.
      if (l == 2) {
        int oid = tid >> 4, s = tid & 15;
        int o = oid & 1, b = oid >> 1;
        float p = 0.0f;
#pragma unroll
        for (int m = 0; m < 8; m++)
          p = fmaf(s_fcw[o * H + s * 8 + m], s_x[(s * 8 + m) * 8 + b], p);
        p += __shfl_down_sync(0xffffffffu, p, 8, 16);
        p += __shfl_down_sync(0xffffffffu, p, 4, 16);
        p += __shfl_down_sync(0xffffffffu, p, 2, 16);
        p += __shfl_down_sync(0xffffffffu, p, 1, 16);
        if (s == 0) out[((b0 + b) * T + t) * 2 + o] = p + s_fcb[o];
      }
      // fc reads of s_x precede the next cell's combine writes (those sit
      // behind the next cell's B1, which waits for every thread's fc).
    }
  }
}

extern "C" void kernel_launch(void* const* d_in, const int* in_sizes, int n_in,
                              void* d_out, int out_size) {
  (void)in_sizes; (void)n_in; (void)out_size;
  const float* hiddens = (const float*)d_in[0];
  const float* W_ih    = (const float*)d_in[1];
  const float* W_hh    = (const float*)d_in[2];
  const float* b_ih    = (const float*)d_in[3];
  const float* b_hh    = (const float*)d_in[4];
  const float* fc_w    = (const float*)d_in[5];
  const float* fc_b    = (const float*)d_in[6];
  float* out = (float*)d_out;

  cudaFuncSetAttribute(gru_kernel, cudaFuncAttributeMaxDynamicSharedMemorySize,
                       SMEM_TOTAL);

  const int prep_elems = 2 * LAYERS * KCH * 6 * NTHR;
  prep_kernel<<<(prep_elems + 255) / 256, 256>>>(W_ih, W_hh);
  gru_kernel<<<NBLK, NTHR, SMEM_TOTAL>>>(hiddens, b_ih, b_hh, fc_w, fc_b, out);
}